// round 9
// baseline (speedup 1.0000x reference)
#include <cuda_runtime.h>
#include <cstdint>

#define N     8192
#define E     262144
#define D     128
#define HMLP  256
#define KEEP  131072
#define CHUNK 1024
#define EQCAP 4096

// ------------------- device scratch (static, zero/value-init at load; -------------------
// ------------------- every kernel leaves its state clean for the next run) --------------
__device__ float    d_XW[N * D];
__device__ float    d_Hv[N * D];
__device__ float    d_G [N * HMLP];
__device__ float    d_part[64 * D];
__device__ float    d_cb[HMLP];
__device__ unsigned d_key[E];
__device__ int      d_row_cnt[N];          // zeroed by csr_scan after use
__device__ int      d_row_cur[N];          // zeroed by gnn_row after use
__device__ int      d_row_start[N + 1];
__device__ int      d_perm[E];
__device__ unsigned d_cand_key[E];
__device__ int      d_cand_edge[E];
__device__ int      d_cand_cnt = 0;        // reset by scatter_eq tail
__device__ unsigned d_hist4[4][256];       // zeroed by scan_pass after use
__device__ unsigned d_prefix = 0u;         // reset by scatter_eq tail
__device__ unsigned d_krem   = KEEP;       // reset by scatter_eq tail
__device__ int      d_eq_cnt = 0;          // reset by scatter_eq tail
__device__ int      d_eq_list[EQCAP];

// ------------------- streaming zero of output (L2-bypass via __stwt) -------------------
__global__ void __launch_bounds__(256) zero_out_stream_kernel(float4* __restrict__ out) {
    const size_t total = (size_t)N * N / 4;
    size_t idx    = (size_t)blockIdx.x * blockDim.x + threadIdx.x;
    size_t stride = (size_t)gridDim.x * blockDim.x;
    const float4 z = make_float4(0.f, 0.f, 0.f, 0.f);
    for (; idx < total; idx += stride) __stwt(&out[idx], z);
}

// ------------------- tiled SGEMM: C[M,NTOT] = A[M,128] @ B[128,NTOT] -------------------
__global__ void __launch_bounds__(256) sgemm_kernel(const float* __restrict__ A,
                                                    const float* __restrict__ B,
                                                    float* __restrict__ C, int NTOT) {
    __shared__ float As[16][65];
    __shared__ float Bs[16][128];
    int t   = threadIdx.x;
    int tx  = t & 15;
    int ty  = t >> 4;
    int r0  = blockIdx.x * 64;
    int n0  = blockIdx.y * 128;

    float acc[4][8];
#pragma unroll
    for (int r = 0; r < 4; r++)
#pragma unroll
        for (int c = 0; c < 8; c++) acc[r][c] = 0.f;

    for (int k0 = 0; k0 < D; k0 += 16) {
        {
            int m  = t >> 2;
            int kq = (t & 3) * 4;
            float4 v = *(const float4*)&A[(size_t)(r0 + m) * D + k0 + kq];
            As[kq + 0][m] = v.x; As[kq + 1][m] = v.y;
            As[kq + 2][m] = v.z; As[kq + 3][m] = v.w;
        }
        {
            int kb = t >> 4;
            int nb = (t & 15) * 8;
            float4 v0 = *(const float4*)&B[(size_t)(k0 + kb) * NTOT + n0 + nb];
            float4 v1 = *(const float4*)&B[(size_t)(k0 + kb) * NTOT + n0 + nb + 4];
            *(float4*)&Bs[kb][nb]     = v0;
            *(float4*)&Bs[kb][nb + 4] = v1;
        }
        __syncthreads();
#pragma unroll
        for (int k = 0; k < 16; k++) {
            float a0 = As[k][ty * 4 + 0], a1 = As[k][ty * 4 + 1];
            float a2 = As[k][ty * 4 + 2], a3 = As[k][ty * 4 + 3];
            float4 b0 = *(float4*)&Bs[k][tx * 8];
            float4 b1 = *(float4*)&Bs[k][tx * 8 + 4];
            float bb[8] = {b0.x, b0.y, b0.z, b0.w, b1.x, b1.y, b1.z, b1.w};
#pragma unroll
            for (int c = 0; c < 8; c++) {
                acc[0][c] = fmaf(a0, bb[c], acc[0][c]);
                acc[1][c] = fmaf(a1, bb[c], acc[1][c]);
                acc[2][c] = fmaf(a2, bb[c], acc[2][c]);
                acc[3][c] = fmaf(a3, bb[c], acc[3][c]);
            }
        }
        __syncthreads();
    }
#pragma unroll
    for (int r = 0; r < 4; r++) {
        float* cp = &C[(size_t)(r0 + ty * 4 + r) * NTOT + n0 + tx * 8];
        *(float4*)cp       = make_float4(acc[r][0], acc[r][1], acc[r][2], acc[r][3]);
        *(float4*)(cp + 4) = make_float4(acc[r][4], acc[r][5], acc[r][6], acc[r][7]);
    }
}

// ------------------- CSR build -------------------
__global__ void hist_ei_kernel(const int4* __restrict__ ei4) {
    int idx = blockIdx.x * blockDim.x + threadIdx.x;
    if (idx < E / 4) {
        int4 v = ei4[idx];
        atomicAdd(&d_row_cnt[v.x], 1);
        atomicAdd(&d_row_cnt[v.y], 1);
        atomicAdd(&d_row_cnt[v.z], 1);
        atomicAdd(&d_row_cnt[v.w], 1);
    }
}

// warp-shuffle scan; self-cleans d_row_cnt
__global__ void __launch_bounds__(1024) csr_scan_kernel() {
    __shared__ int wsum[32];
    int t = threadIdx.x, lane = t & 31, warp = t >> 5;
    int4 c0 = *(const int4*)&d_row_cnt[t * 8];
    int4 c1 = *(const int4*)&d_row_cnt[t * 8 + 4];
    const int4 z4 = make_int4(0, 0, 0, 0);
    *(int4*)&d_row_cnt[t * 8]     = z4;          // self-clean for next run
    *(int4*)&d_row_cnt[t * 8 + 4] = z4;
    int cnt[8] = {c0.x, c0.y, c0.z, c0.w, c1.x, c1.y, c1.z, c1.w};
    int loc[8]; int s = 0;
#pragma unroll
    for (int k = 0; k < 8; k++) { loc[k] = s; s += cnt[k]; }
    int v = s;
#pragma unroll
    for (int off = 1; off < 32; off <<= 1) {
        int n = __shfl_up_sync(0xFFFFFFFFu, v, off);
        if (lane >= off) v += n;
    }
    if (lane == 31) wsum[warp] = v;
    __syncthreads();
    if (warp == 0) {
        int w = wsum[lane];
#pragma unroll
        for (int off = 1; off < 32; off <<= 1) {
            int n = __shfl_up_sync(0xFFFFFFFFu, w, off);
            if (lane >= off) w += n;
        }
        wsum[lane] = w;
    }
    __syncthreads();
    int excl = v - s + (warp ? wsum[warp - 1] : 0);
#pragma unroll
    for (int k = 0; k < 8; k++) d_row_start[t * 8 + k] = excl + loc[k];
    if (t == 1023) d_row_start[N] = excl + s;
}

// scalar: 1 edge per thread (4 independent atomic chains per warp-slot, more MLP)
__global__ void scatter_perm_kernel(const int* __restrict__ ei) {
    int e = blockIdx.x * blockDim.x + threadIdx.x;
    if (e < E) {
        int i   = ei[e];
        int pos = d_row_start[i] + atomicAdd(&d_row_cur[i], 1);
        d_perm[pos] = e;
    }
}

// ---- H_v rows: sparse A@XW + relu (dedup'd); self-cleans d_row_cur[i] ----
__global__ void __launch_bounds__(128) gnn_row_kernel(const float* __restrict__ A,
                                                      const int*   __restrict__ ej,
                                                      const float* __restrict__ b_gnn) {
    __shared__ unsigned bm[256];
    __shared__ int      sj[CHUNK];
    __shared__ float    sw[CHUNK];
    int i = blockIdx.x, t = threadIdx.x;
    if (t == 0) d_row_cur[i] = 0;                 // self-clean for next run
    for (int k = t; k < 256; k += 128) bm[k] = 0u;
    int s0 = d_row_start[i], s1 = d_row_start[i + 1];
    __syncthreads();
    float acc = 0.f;
    for (int base = s0; base < s1; base += CHUNK) {
        int cnt = min(CHUNK, s1 - base);
        for (int s = t; s < cnt; s += 128) {
            int e = d_perm[base + s];
            int j = ej[e];
            unsigned old = atomicOr(&bm[j >> 5], 1u << (j & 31));
            bool dup = (old >> (j & 31)) & 1u;
            sj[s] = dup ? -1 : j;
            sw[s] = dup ? 0.f : A[(size_t)i * N + j];
        }
        __syncthreads();
        for (int s = 0; s < cnt; s++) {
            int j = sj[s];
            if (j >= 0) acc = fmaf(sw[s], d_XW[j * D + t], acc);
        }
        __syncthreads();
    }
    d_Hv[i * D + t] = fmaxf(acc + b_gnn[t], 0.f);
}

// ------------------- h_G partials + fused (mean + cb) -------------------
__global__ void hg1_kernel() {
    int b = blockIdx.x, d = threadIdx.x;
    float acc = 0.f;
    for (int r = 0; r < 128; r++) acc += d_Hv[(b * 128 + r) * D + d];
    d_part[b * D + d] = acc;
}

__global__ void hg2cb_kernel(const float* __restrict__ W1, const float* __restrict__ b1) {
    __shared__ float hg[D];
    int t = threadIdx.x;
    if (t < D) {
        float acc = 0.f;
        for (int b = 0; b < 64; b++) acc += d_part[b * D + t];
        hg[t] = acc * (1.f / N);
    }
    __syncthreads();
    float acc = 0.f;
    for (int dd = 0; dd < D; dd++) acc = fmaf(hg[dd], W1[(D + dd) * HMLP + t], acc);
    d_cb[t] = acc + W1[(2 * D) * HMLP + t] + b1[t];
}

// ------- per-edge scores, CSR-ordered, fused level-0 histogram (smem, 1 atomic/bin) -------
__global__ void __launch_bounds__(256) score_csr_kernel(const int*   __restrict__ ej,
                                                        const float* __restrict__ noise,
                                                        const float* __restrict__ W2,
                                                        const float* __restrict__ b2) {
    __shared__ float gis[HMLP];
    __shared__ float cbs[HMLP];
    __shared__ float w2s[HMLP];
    __shared__ unsigned bh[256];
    int i  = blockIdx.x;
    int s0 = d_row_start[i], s1 = d_row_start[i + 1];
    if (s0 == s1) return;
    int t = threadIdx.x;
    gis[t] = d_G[(size_t)i * HMLP + t];
    cbs[t] = d_cb[t];
    w2s[t] = W2[t];
    bh[t]  = 0u;
    __syncthreads();
    int warp = t >> 5, lane = t & 31;
    float b2v = b2[0];
    for (int idx = s0 + warp; idx < s1; idx += 8) {
        int e = d_perm[idx];
        int j = ej[e];
        const float* gj = d_G + (size_t)j * HMLP;
        float acc = 0.f;
#pragma unroll
        for (int q = 0; q < 8; q++) {
            int o = lane + 32 * q;
            float h = fmaxf((gis[o] + __ldg(&gj[o])) + cbs[o], 0.f);
            acc = fmaf(h, w2s[o], acc);
        }
        for (int off = 16; off; off >>= 1) acc += __shfl_xor_sync(0xFFFFFFFFu, acc, off);
        if (lane == 0) {
            float u = noise[e];
            float g = -logf(-logf(u + 1e-8f) + 1e-8f);
            float s = acc + b2v + g;
            unsigned k = __float_as_uint(s);
            k = (k & 0x80000000u) ? ~k : (k | 0x80000000u);
            d_key[e] = k;
            atomicAdd(&bh[k >> 24], 1u);
        }
    }
    __syncthreads();
    if (bh[t]) atomicAdd(&d_hist4[0][t], bh[t]);
}

// 256-thread suffix-sum scan over bins (descending); zeroes its hist level after use
__global__ void __launch_bounds__(256) scan_pass_kernel(int level) {
    __shared__ unsigned sh[256];
    int shift = 24 - 8 * level;
    int t = threadIdx.x;
    unsigned h = d_hist4[level][t];
    sh[t] = h;
    __syncthreads();
    for (int off = 1; off < 256; off <<= 1) {
        unsigned add = (t + off < 256) ? sh[t + off] : 0u;
        __syncthreads();
        sh[t] += add;
        __syncthreads();
    }
    unsigned S  = sh[t];
    unsigned Sn = (t < 255) ? sh[t + 1] : 0u;
    unsigned krem = d_krem;
    if (S >= krem && Sn < krem) {               // exactly one thread
        atomicOr(&d_prefix, ((unsigned)t) << shift);
        d_krem = krem - Sn;
    }
    d_hist4[level][t] = 0u;                     // self-clean for next run
}

// ---- compact candidates (top byte == prefix0) + fused level-1 histogram ----
__global__ void __launch_bounds__(256) compact_hist1_kernel() {
    __shared__ unsigned bh[256];
    int t = threadIdx.x;
    bh[t] = 0u;
    __syncthreads();
    unsigned p0 = d_prefix >> 24;
    for (int e = blockIdx.x * blockDim.x + t; e < E; e += gridDim.x * blockDim.x) {
        unsigned u = d_key[e];
        if ((u >> 24) == p0) {
            int pos = atomicAdd(&d_cand_cnt, 1);
            d_cand_key[pos]  = u;
            d_cand_edge[pos] = e;
            atomicAdd(&bh[(u >> 16) & 255], 1u);
        }
    }
    __syncthreads();
    if (bh[t]) atomicAdd(&d_hist4[1][t], bh[t]);
}

// ---- histogram over candidates for levels 2,3 ----
__global__ void __launch_bounds__(256) hist_cand_kernel(int level) {
    __shared__ unsigned bh[256];
    int t = threadIdx.x;
    bh[t] = 0u;
    __syncthreads();
    int shift = 24 - 8 * level;
    unsigned pfxhi = d_prefix >> (shift + 8);
    int cnt = d_cand_cnt;
    for (int idx = blockIdx.x * blockDim.x + t; idx < cnt; idx += gridDim.x * blockDim.x) {
        unsigned u = d_cand_key[idx];
        if ((u >> (shift + 8)) == pfxhi) atomicAdd(&bh[(u >> shift) & 255], 1u);
    }
    __syncthreads();
    if (bh[t]) atomicAdd(&d_hist4[level][t], bh[t]);
}

// ------------------- output scatter (gt + eq-collect fused) -------------------
__global__ void scatter_gt_eq_kernel(const float* __restrict__ A,
                                     const int* __restrict__ ei, const int* __restrict__ ej,
                                     float* __restrict__ out) {
    unsigned th = d_prefix;
    for (int e = blockIdx.x * blockDim.x + threadIdx.x; e < E;
         e += gridDim.x * blockDim.x) {
        unsigned u = d_key[e];
        if (u > th) {
            int i = ei[e], j = ej[e];
            out[(size_t)i * N + j] = A[(size_t)i * N + j];
        } else if (u == th) {
            int p = atomicAdd(&d_eq_cnt, 1);
            if (p < EQCAP) d_eq_list[p] = e;
        }
    }
}

// single block: scatter boundary-equal edges (tie-break lowest index), then reset scalars
__global__ void __launch_bounds__(1024) scatter_eq_reset_kernel(
        const float* __restrict__ A,
        const int* __restrict__ ei, const int* __restrict__ ej,
        float* __restrict__ out) {
    int cnt  = min(d_eq_cnt, EQCAP);
    int need = (int)d_krem;
    for (int tid = threadIdx.x; tid < cnt; tid += 1024) {
        int my = d_eq_list[tid];
        int r = 0;
        for (int t2 = 0; t2 < cnt; t2++) r += (d_eq_list[t2] < my);
        if (r < need) {
            int i = ei[my], j = ej[my];
            out[(size_t)i * N + j] = A[(size_t)i * N + j];
        }
    }
    __syncthreads();
    if (threadIdx.x == 0) {
        d_prefix   = 0u;
        d_krem     = KEEP;
        d_eq_cnt   = 0;
        d_cand_cnt = 0;
    }
}

// ------------------- launch (fork/join graph branches) -------------------
extern "C" void kernel_launch(void* const* d_in, const int* in_sizes, int n_in,
                              void* d_out, int out_size) {
    const float* A      = (const float*)d_in[0];
    const float* X      = (const float*)d_in[1];
    const int*   ei     = (const int*)  d_in[2];
    const int*   ej     = (const int*)  d_in[3];
    const float* noise  = (const float*)d_in[4];
    const float* W_gnn  = (const float*)d_in[5];
    const float* b_gnn  = (const float*)d_in[6];
    const float* W1     = (const float*)d_in[7];
    const float* b1     = (const float*)d_in[8];
    const float* W2     = (const float*)d_in[9];
    const float* b2     = (const float*)d_in[10];
    float* out = (float*)d_out;

    static cudaStream_t s_zero = nullptr, s_csr = nullptr;
    static cudaEvent_t  ev_root, ev_zero_done, ev_csr_done, ev_gnn_done, ev_hg_done;
    if (!s_zero) {
        cudaStreamCreateWithFlags(&s_zero, cudaStreamNonBlocking);
        cudaStreamCreateWithFlags(&s_csr,  cudaStreamNonBlocking);
        cudaEventCreateWithFlags(&ev_root,      cudaEventDisableTiming);
        cudaEventCreateWithFlags(&ev_zero_done, cudaEventDisableTiming);
        cudaEventCreateWithFlags(&ev_csr_done,  cudaEventDisableTiming);
        cudaEventCreateWithFlags(&ev_gnn_done,  cudaEventDisableTiming);
        cudaEventCreateWithFlags(&ev_hg_done,   cudaEventDisableTiming);
    }

    float* xw_p; cudaGetSymbolAddress((void**)&xw_p, d_XW);
    float* hv_p; cudaGetSymbolAddress((void**)&hv_p, d_Hv);
    float* g_p;  cudaGetSymbolAddress((void**)&g_p,  d_G);

    cudaEventRecord(ev_root, 0);

    // branch 1: streaming zero of 256MB output, joins before scatter
    cudaStreamWaitEvent(s_zero, ev_root, 0);
    zero_out_stream_kernel<<<1024, 256, 0, s_zero>>>((float4*)out);
    cudaEventRecord(ev_zero_done, s_zero);

    // branch 2: CSR build, joins before gnn_row
    cudaStreamWaitEvent(s_csr, ev_root, 0);
    hist_ei_kernel<<<E / 4 / 256, 256, 0, s_csr>>>((const int4*)ei);
    csr_scan_kernel<<<1, 1024, 0, s_csr>>>();
    scatter_perm_kernel<<<E / 256, 256, 0, s_csr>>>(ei);
    cudaEventRecord(ev_csr_done, s_csr);

    // main branch: XW gemm parallel to CSR build
    sgemm_kernel<<<dim3(N / 64, 1), 256>>>(X, W_gnn, xw_p, D);

    cudaStreamWaitEvent(0, ev_csr_done, 0);
    gnn_row_kernel<<<N, 128>>>(A, ej, b_gnn);
    cudaEventRecord(ev_gnn_done, 0);

    // fork: hg chain on side stream, sgemm2 on main — both depend only on Hv
    cudaStreamWaitEvent(s_csr, ev_gnn_done, 0);
    hg1_kernel<<<64, 128, 0, s_csr>>>();
    hg2cb_kernel<<<1, 256, 0, s_csr>>>(W1, b1);
    cudaEventRecord(ev_hg_done, s_csr);

    sgemm_kernel<<<dim3(N / 64, 2), 256>>>(hv_p, W1, g_p, HMLP);

    cudaStreamWaitEvent(0, ev_hg_done, 0);
    score_csr_kernel<<<N, 256>>>(ej, noise, W2, b2);   // includes hist level 0

    scan_pass_kernel<<<1, 256>>>(0);
    compact_hist1_kernel<<<512, 256>>>();              // compacts + hist level 1
    scan_pass_kernel<<<1, 256>>>(1);
    hist_cand_kernel<<<256, 256>>>(2);
    scan_pass_kernel<<<1, 256>>>(2);
    hist_cand_kernel<<<256, 256>>>(3);
    scan_pass_kernel<<<1, 256>>>(3);

    cudaStreamWaitEvent(0, ev_zero_done, 0);
    scatter_gt_eq_kernel<<<1024, 256>>>(A, ei, ej, out);
    scatter_eq_reset_kernel<<<1, 1024>>>(A, ei, ej, out);
}

// round 10
// speedup vs baseline: 1.0251x; 1.0251x over previous
#include <cuda_runtime.h>
#include <cstdint>

#define N     8192
#define E     262144
#define D     128
#define HMLP  256
#define KEEP  131072
#define CHUNK 1024
#define EQCAP 4096

// ------------------- device scratch (static, zero/value-init at load; -------------------
// ------------------- every kernel leaves its state clean for the next run) --------------
__device__ float    d_XW[N * D];
__device__ float    d_Hv[N * D];
__device__ float    d_G [N * HMLP];
__device__ float    d_part[64 * D];
__device__ float    d_cb[HMLP];
__device__ unsigned d_key[E];
__device__ int      d_row_cnt[N];          // zeroed by csr_scan after use
__device__ int      d_row_cur[N];          // zeroed by gnn_row after use
__device__ int      d_row_start[N + 1];
__device__ int      d_perm[E];
__device__ unsigned d_hist4[4][256];       // zeroed by scan_pass after use
__device__ unsigned d_prefix = 0u;         // reset by scatter_eq_reset tail
__device__ unsigned d_krem   = KEEP;       // reset by scatter_eq_reset tail
__device__ int      d_eq_cnt = 0;          // reset by scatter_eq_reset tail
__device__ int      d_eq_list[EQCAP];

// ------------------- streaming zero of output (L2-bypass via __stwt) -------------------
__global__ void __launch_bounds__(256) zero_out_stream_kernel(float4* __restrict__ out) {
    const size_t total = (size_t)N * N / 4;
    size_t idx    = (size_t)blockIdx.x * blockDim.x + threadIdx.x;
    size_t stride = (size_t)gridDim.x * blockDim.x;
    const float4 z = make_float4(0.f, 0.f, 0.f, 0.f);
    for (; idx < total; idx += stride) __stwt(&out[idx], z);
}

// ------------------- tiled SGEMM: C[M,NTOT] = A[M,128] @ B[128,NTOT] -------------------
__global__ void __launch_bounds__(256) sgemm_kernel(const float* __restrict__ A,
                                                    const float* __restrict__ B,
                                                    float* __restrict__ C, int NTOT) {
    __shared__ float As[16][65];
    __shared__ float Bs[16][128];
    int t   = threadIdx.x;
    int tx  = t & 15;
    int ty  = t >> 4;
    int r0  = blockIdx.x * 64;
    int n0  = blockIdx.y * 128;

    float acc[4][8];
#pragma unroll
    for (int r = 0; r < 4; r++)
#pragma unroll
        for (int c = 0; c < 8; c++) acc[r][c] = 0.f;

    for (int k0 = 0; k0 < D; k0 += 16) {
        {
            int m  = t >> 2;
            int kq = (t & 3) * 4;
            float4 v = *(const float4*)&A[(size_t)(r0 + m) * D + k0 + kq];
            As[kq + 0][m] = v.x; As[kq + 1][m] = v.y;
            As[kq + 2][m] = v.z; As[kq + 3][m] = v.w;
        }
        {
            int kb = t >> 4;
            int nb = (t & 15) * 8;
            float4 v0 = *(const float4*)&B[(size_t)(k0 + kb) * NTOT + n0 + nb];
            float4 v1 = *(const float4*)&B[(size_t)(k0 + kb) * NTOT + n0 + nb + 4];
            *(float4*)&Bs[kb][nb]     = v0;
            *(float4*)&Bs[kb][nb + 4] = v1;
        }
        __syncthreads();
#pragma unroll
        for (int k = 0; k < 16; k++) {
            float a0 = As[k][ty * 4 + 0], a1 = As[k][ty * 4 + 1];
            float a2 = As[k][ty * 4 + 2], a3 = As[k][ty * 4 + 3];
            float4 b0 = *(float4*)&Bs[k][tx * 8];
            float4 b1 = *(float4*)&Bs[k][tx * 8 + 4];
            float bb[8] = {b0.x, b0.y, b0.z, b0.w, b1.x, b1.y, b1.z, b1.w};
#pragma unroll
            for (int c = 0; c < 8; c++) {
                acc[0][c] = fmaf(a0, bb[c], acc[0][c]);
                acc[1][c] = fmaf(a1, bb[c], acc[1][c]);
                acc[2][c] = fmaf(a2, bb[c], acc[2][c]);
                acc[3][c] = fmaf(a3, bb[c], acc[3][c]);
            }
        }
        __syncthreads();
    }
#pragma unroll
    for (int r = 0; r < 4; r++) {
        float* cp = &C[(size_t)(r0 + ty * 4 + r) * NTOT + n0 + tx * 8];
        *(float4*)cp       = make_float4(acc[r][0], acc[r][1], acc[r][2], acc[r][3]);
        *(float4*)(cp + 4) = make_float4(acc[r][4], acc[r][5], acc[r][6], acc[r][7]);
    }
}

// ------------------- CSR build -------------------
__global__ void hist_ei_kernel(const int4* __restrict__ ei4) {
    int idx = blockIdx.x * blockDim.x + threadIdx.x;
    if (idx < E / 4) {
        int4 v = ei4[idx];
        atomicAdd(&d_row_cnt[v.x], 1);
        atomicAdd(&d_row_cnt[v.y], 1);
        atomicAdd(&d_row_cnt[v.z], 1);
        atomicAdd(&d_row_cnt[v.w], 1);
    }
}

// warp-shuffle scan; self-cleans d_row_cnt
__global__ void __launch_bounds__(1024) csr_scan_kernel() {
    __shared__ int wsum[32];
    int t = threadIdx.x, lane = t & 31, warp = t >> 5;
    int4 c0 = *(const int4*)&d_row_cnt[t * 8];
    int4 c1 = *(const int4*)&d_row_cnt[t * 8 + 4];
    const int4 z4 = make_int4(0, 0, 0, 0);
    *(int4*)&d_row_cnt[t * 8]     = z4;          // self-clean for next run
    *(int4*)&d_row_cnt[t * 8 + 4] = z4;
    int cnt[8] = {c0.x, c0.y, c0.z, c0.w, c1.x, c1.y, c1.z, c1.w};
    int loc[8]; int s = 0;
#pragma unroll
    for (int k = 0; k < 8; k++) { loc[k] = s; s += cnt[k]; }
    int v = s;
#pragma unroll
    for (int off = 1; off < 32; off <<= 1) {
        int n = __shfl_up_sync(0xFFFFFFFFu, v, off);
        if (lane >= off) v += n;
    }
    if (lane == 31) wsum[warp] = v;
    __syncthreads();
    if (warp == 0) {
        int w = wsum[lane];
#pragma unroll
        for (int off = 1; off < 32; off <<= 1) {
            int n = __shfl_up_sync(0xFFFFFFFFu, w, off);
            if (lane >= off) w += n;
        }
        wsum[lane] = w;
    }
    __syncthreads();
    int excl = v - s + (warp ? wsum[warp - 1] : 0);
#pragma unroll
    for (int k = 0; k < 8; k++) d_row_start[t * 8 + k] = excl + loc[k];
    if (t == 1023) d_row_start[N] = excl + s;
}

__global__ void scatter_perm_kernel(const int* __restrict__ ei) {
    int e = blockIdx.x * blockDim.x + threadIdx.x;
    if (e < E) {
        int i   = ei[e];
        int pos = d_row_start[i] + atomicAdd(&d_row_cur[i], 1);
        d_perm[pos] = e;
    }
}

// ---- H_v rows: sparse A@XW + relu (dedup'd); self-cleans d_row_cur[i] ----
__global__ void __launch_bounds__(128) gnn_row_kernel(const float* __restrict__ A,
                                                      const int*   __restrict__ ej,
                                                      const float* __restrict__ b_gnn) {
    __shared__ unsigned bm[256];
    __shared__ int      sj[CHUNK];
    __shared__ float    sw[CHUNK];
    int i = blockIdx.x, t = threadIdx.x;
    if (t == 0) d_row_cur[i] = 0;                 // self-clean for next run
    for (int k = t; k < 256; k += 128) bm[k] = 0u;
    int s0 = d_row_start[i], s1 = d_row_start[i + 1];
    __syncthreads();
    float acc = 0.f;
    for (int base = s0; base < s1; base += CHUNK) {
        int cnt = min(CHUNK, s1 - base);
        for (int s = t; s < cnt; s += 128) {
            int e = d_perm[base + s];
            int j = ej[e];
            unsigned old = atomicOr(&bm[j >> 5], 1u << (j & 31));
            bool dup = (old >> (j & 31)) & 1u;
            sj[s] = dup ? -1 : j;
            sw[s] = dup ? 0.f : A[(size_t)i * N + j];
        }
        __syncthreads();
        for (int s = 0; s < cnt; s++) {
            int j = sj[s];
            if (j >= 0) acc = fmaf(sw[s], d_XW[j * D + t], acc);
        }
        __syncthreads();
    }
    d_Hv[i * D + t] = fmaxf(acc + b_gnn[t], 0.f);
}

// ------------------- h_G partials + fused (mean + cb) -------------------
__global__ void hg1_kernel() {
    int b = blockIdx.x, d = threadIdx.x;
    float acc = 0.f;
    for (int r = 0; r < 128; r++) acc += d_Hv[(b * 128 + r) * D + d];
    d_part[b * D + d] = acc;
}

__global__ void hg2cb_kernel(const float* __restrict__ W1, const float* __restrict__ b1) {
    __shared__ float hg[D];
    int t = threadIdx.x;
    if (t < D) {
        float acc = 0.f;
        for (int b = 0; b < 64; b++) acc += d_part[b * D + t];
        hg[t] = acc * (1.f / N);
    }
    __syncthreads();
    float acc = 0.f;
    for (int dd = 0; dd < D; dd++) acc = fmaf(hg[dd], W1[(D + dd) * HMLP + t], acc);
    d_cb[t] = acc + W1[(2 * D) * HMLP + t] + b1[t];
}

// ------- per-edge scores, CSR-ordered, fused level-0 histogram (smem, 1 atomic/bin) -------
__global__ void __launch_bounds__(256) score_csr_kernel(const int*   __restrict__ ej,
                                                        const float* __restrict__ noise,
                                                        const float* __restrict__ W2,
                                                        const float* __restrict__ b2) {
    __shared__ float gis[HMLP];
    __shared__ float cbs[HMLP];
    __shared__ float w2s[HMLP];
    __shared__ unsigned bh[256];
    int i  = blockIdx.x;
    int s0 = d_row_start[i], s1 = d_row_start[i + 1];
    if (s0 == s1) return;
    int t = threadIdx.x;
    gis[t] = d_G[(size_t)i * HMLP + t];
    cbs[t] = d_cb[t];
    w2s[t] = W2[t];
    bh[t]  = 0u;
    __syncthreads();
    int warp = t >> 5, lane = t & 31;
    float b2v = b2[0];
    for (int idx = s0 + warp; idx < s1; idx += 8) {
        int e = d_perm[idx];
        int j = ej[e];
        const float* gj = d_G + (size_t)j * HMLP;
        float acc = 0.f;
#pragma unroll
        for (int q = 0; q < 8; q++) {
            int o = lane + 32 * q;
            float h = fmaxf((gis[o] + __ldg(&gj[o])) + cbs[o], 0.f);
            acc = fmaf(h, w2s[o], acc);
        }
        for (int off = 16; off; off >>= 1) acc += __shfl_xor_sync(0xFFFFFFFFu, acc, off);
        if (lane == 0) {
            float u = noise[e];
            float g = -logf(-logf(u + 1e-8f) + 1e-8f);
            float s = acc + b2v + g;
            unsigned k = __float_as_uint(s);
            k = (k & 0x80000000u) ? ~k : (k | 0x80000000u);
            d_key[e] = k;
            atomicAdd(&bh[k >> 24], 1u);
        }
    }
    __syncthreads();
    if (bh[t]) atomicAdd(&d_hist4[0][t], bh[t]);
}

// ------------------- radix hist over full keys (levels 1..3) -------------------
__global__ void hist_pass_kernel(int level) {
    __shared__ unsigned sh[256];
    int shift = 24 - 8 * level;
    unsigned himask = 0xFFFFFFFFu << (shift + 8);
    unsigned pfx = d_prefix;
    for (int k = threadIdx.x; k < 256; k += blockDim.x) sh[k] = 0u;
    __syncthreads();
    for (int e = blockIdx.x * blockDim.x + threadIdx.x; e < E;
         e += gridDim.x * blockDim.x) {
        unsigned u = d_key[e];
        if ((u & himask) == pfx) atomicAdd(&sh[(u >> shift) & 255], 1u);
    }
    __syncthreads();
    for (int k = threadIdx.x; k < 256; k += blockDim.x)
        if (sh[k]) atomicAdd(&d_hist4[level][k], sh[k]);
}

// 256-thread suffix-sum scan over bins (descending); zeroes its hist level after use
__global__ void __launch_bounds__(256) scan_pass_kernel(int level) {
    __shared__ unsigned sh[256];
    int shift = 24 - 8 * level;
    int t = threadIdx.x;
    unsigned h = d_hist4[level][t];
    sh[t] = h;
    __syncthreads();
    for (int off = 1; off < 256; off <<= 1) {
        unsigned add = (t + off < 256) ? sh[t + off] : 0u;
        __syncthreads();
        sh[t] += add;
        __syncthreads();
    }
    unsigned S  = sh[t];
    unsigned Sn = (t < 255) ? sh[t + 1] : 0u;
    unsigned krem = d_krem;
    if (S >= krem && Sn < krem) {               // exactly one thread
        atomicOr(&d_prefix, ((unsigned)t) << shift);
        d_krem = krem - Sn;
    }
    d_hist4[level][t] = 0u;                     // self-clean for next run
}

// ------------------- output scatter (gt + eq-collect fused) -------------------
__global__ void scatter_gt_eq_kernel(const float* __restrict__ A,
                                     const int* __restrict__ ei, const int* __restrict__ ej,
                                     float* __restrict__ out) {
    unsigned th = d_prefix;
    for (int e = blockIdx.x * blockDim.x + threadIdx.x; e < E;
         e += gridDim.x * blockDim.x) {
        unsigned u = d_key[e];
        if (u > th) {
            int i = ei[e], j = ej[e];
            out[(size_t)i * N + j] = A[(size_t)i * N + j];
        } else if (u == th) {
            int p = atomicAdd(&d_eq_cnt, 1);
            if (p < EQCAP) d_eq_list[p] = e;
        }
    }
}

// single block: scatter boundary-equal edges (tie-break lowest index), then reset scalars
__global__ void __launch_bounds__(1024) scatter_eq_reset_kernel(
        const float* __restrict__ A,
        const int* __restrict__ ei, const int* __restrict__ ej,
        float* __restrict__ out) {
    int cnt  = min(d_eq_cnt, EQCAP);
    int need = (int)d_krem;
    for (int tid = threadIdx.x; tid < cnt; tid += 1024) {
        int my = d_eq_list[tid];
        int r = 0;
        for (int t2 = 0; t2 < cnt; t2++) r += (d_eq_list[t2] < my);
        if (r < need) {
            int i = ei[my], j = ej[my];
            out[(size_t)i * N + j] = A[(size_t)i * N + j];
        }
    }
    __syncthreads();
    if (threadIdx.x == 0) {
        d_prefix = 0u;
        d_krem   = KEEP;
        d_eq_cnt = 0;
    }
}

// ------------------- launch (fork/join graph branches) -------------------
extern "C" void kernel_launch(void* const* d_in, const int* in_sizes, int n_in,
                              void* d_out, int out_size) {
    const float* A      = (const float*)d_in[0];
    const float* X      = (const float*)d_in[1];
    const int*   ei     = (const int*)  d_in[2];
    const int*   ej     = (const int*)  d_in[3];
    const float* noise  = (const float*)d_in[4];
    const float* W_gnn  = (const float*)d_in[5];
    const float* b_gnn  = (const float*)d_in[6];
    const float* W1     = (const float*)d_in[7];
    const float* b1     = (const float*)d_in[8];
    const float* W2     = (const float*)d_in[9];
    const float* b2     = (const float*)d_in[10];
    float* out = (float*)d_out;

    static cudaStream_t s_zero = nullptr, s_csr = nullptr;
    static cudaEvent_t  ev_root, ev_zero_done, ev_csr_done, ev_gnn_done, ev_hg_done;
    if (!s_zero) {
        cudaStreamCreateWithFlags(&s_zero, cudaStreamNonBlocking);
        cudaStreamCreateWithFlags(&s_csr,  cudaStreamNonBlocking);
        cudaEventCreateWithFlags(&ev_root,      cudaEventDisableTiming);
        cudaEventCreateWithFlags(&ev_zero_done, cudaEventDisableTiming);
        cudaEventCreateWithFlags(&ev_csr_done,  cudaEventDisableTiming);
        cudaEventCreateWithFlags(&ev_gnn_done,  cudaEventDisableTiming);
        cudaEventCreateWithFlags(&ev_hg_done,   cudaEventDisableTiming);
    }

    float* xw_p; cudaGetSymbolAddress((void**)&xw_p, d_XW);
    float* hv_p; cudaGetSymbolAddress((void**)&hv_p, d_Hv);
    float* g_p;  cudaGetSymbolAddress((void**)&g_p,  d_G);

    cudaEventRecord(ev_root, 0);

    // branch 1: streaming zero of 256MB output, joins before scatter
    cudaStreamWaitEvent(s_zero, ev_root, 0);
    zero_out_stream_kernel<<<1024, 256, 0, s_zero>>>((float4*)out);
    cudaEventRecord(ev_zero_done, s_zero);

    // branch 2: CSR build, joins before gnn_row
    cudaStreamWaitEvent(s_csr, ev_root, 0);
    hist_ei_kernel<<<E / 4 / 256, 256, 0, s_csr>>>((const int4*)ei);
    csr_scan_kernel<<<1, 1024, 0, s_csr>>>();
    scatter_perm_kernel<<<E / 256, 256, 0, s_csr>>>(ei);
    cudaEventRecord(ev_csr_done, s_csr);

    // main branch: XW gemm parallel to CSR build
    sgemm_kernel<<<dim3(N / 64, 1), 256>>>(X, W_gnn, xw_p, D);

    cudaStreamWaitEvent(0, ev_csr_done, 0);
    gnn_row_kernel<<<N, 128>>>(A, ej, b_gnn);
    cudaEventRecord(ev_gnn_done, 0);

    // fork: hg chain on side stream, sgemm2 on main — both depend only on Hv
    cudaStreamWaitEvent(s_csr, ev_gnn_done, 0);
    hg1_kernel<<<64, 128, 0, s_csr>>>();
    hg2cb_kernel<<<1, 256, 0, s_csr>>>(W1, b1);
    cudaEventRecord(ev_hg_done, s_csr);

    sgemm_kernel<<<dim3(N / 64, 2), 256>>>(hv_p, W1, g_p, HMLP);

    cudaStreamWaitEvent(0, ev_hg_done, 0);
    score_csr_kernel<<<N, 256>>>(ej, noise, W2, b2);   // includes hist level 0

    scan_pass_kernel<<<1, 256>>>(0);
    hist_pass_kernel<<<512, 256>>>(1);
    scan_pass_kernel<<<1, 256>>>(1);
    hist_pass_kernel<<<512, 256>>>(2);
    scan_pass_kernel<<<1, 256>>>(2);
    hist_pass_kernel<<<512, 256>>>(3);
    scan_pass_kernel<<<1, 256>>>(3);

    cudaStreamWaitEvent(0, ev_zero_done, 0);
    scatter_gt_eq_kernel<<<1024, 256>>>(A, ei, ej, out);
    scatter_eq_reset_kernel<<<1, 1024>>>(A, ei, ej, out);
}